// round 12
// baseline (speedup 1.0000x reference)
#include <cuda_runtime.h>
#include <cuda_fp16.h>
#include <cstdint>

#define D_DIM 64
#define K_DIM 512
#define TILE_ROWS 64
#define THREADS 512
#define NBLOCKS 148
#define MARGIN 0.2f

#define APITCH 72        // A/B smem pitch in halves (144B: ldmatrix conflict-free)
#define DPITCH 514       // dist pitch in floats

// ---------------- device scratch (no cudaMalloc allowed) ----------------
__device__ float g_Et[K_DIM * D_DIM];    // exact fp32 E, code-major [k][d]

// ---------------- smem layout (bytes) ----------------
#define SM_A     0                                   // [64][72] half   = 9216
#define SM_B     (SM_A + TILE_ROWS * APITCH * 2)     // [512][72] half  = 73728
#define SM_SE2   (SM_B + K_DIM * APITCH * 2)         // [512] f32       = 2048
#define SM_PVAL  (SM_SE2 + K_DIM * 4)                // [4][64] f32     = 1024
#define SM_RTHR  (SM_PVAL + 4 * TILE_ROWS * 4)       // [64] f32        = 256
#define SM_KFIN  (SM_RTHR + TILE_ROWS * 4)           // [64] i32        = 256
#define SM_DIST  (SM_KFIN + TILE_ROWS * 4)           // [64][514] f32   = 131584
#define SM_TOTAL (SM_DIST + TILE_ROWS * DPITCH * 4)  // 218112 < 232448

__device__ __forceinline__ uint32_t smem_u32(const void* p) {
    uint32_t a;
    asm("{ .reg .u64 t; cvta.to.shared.u64 t, %1; cvt.u32.u64 %0, t; }" : "=r"(a) : "l"(p));
    return a;
}
__device__ __forceinline__ void ldsm_x4(uint32_t* r, uint32_t addr) {
    asm volatile("ldmatrix.sync.aligned.m8n8.x4.shared.b16 {%0,%1,%2,%3}, [%4];"
                 : "=r"(r[0]), "=r"(r[1]), "=r"(r[2]), "=r"(r[3]) : "r"(addr));
}
__device__ __forceinline__ void ldsm_x2(uint32_t* r, uint32_t addr) {
    asm volatile("ldmatrix.sync.aligned.m8n8.x2.shared.b16 {%0,%1}, [%2];"
                 : "=r"(r[0]), "=r"(r[1]) : "r"(addr));
}
__device__ __forceinline__ void mma16816(float* c, const uint32_t* a, const uint32_t* b) {
    asm volatile("mma.sync.aligned.m16n8k16.row.col.f32.f16.f16.f32 "
                 "{%0,%1,%2,%3}, {%4,%5,%6,%7}, {%8,%9}, {%0,%1,%2,%3};"
                 : "+f"(c[0]), "+f"(c[1]), "+f"(c[2]), "+f"(c[3])
                 : "r"(a[0]), "r"(a[1]), "r"(a[2]), "r"(a[3]), "r"(b[0]), "r"(b[1]));
}

// ---------------- prep: transpose E to code-major ----------------
__global__ void vq_prep(const float* __restrict__ emb) {
    int i = blockIdx.x * blockDim.x + threadIdx.x;
    if (i < K_DIM * D_DIM) {
        int k = i / D_DIM, d = i % D_DIM;
        g_Et[i] = emb[d * K_DIM + k];
    }
}

// ---------------- main ----------------
__global__ void __launch_bounds__(THREADS, 1)
vq_main(const float* __restrict__ x, float* __restrict__ out, int nrows, int ntiles)
{
    extern __shared__ char smem[];
    __half* sA   = (__half*)(smem + SM_A);
    __half* sB   = (__half*)(smem + SM_B);
    float*  se2s = (float*) (smem + SM_SE2);
    float*  pval = (float*) (smem + SM_PVAL);
    float*  rthr = (float*) (smem + SM_RTHR);
    int*    kfin = (int*)   (smem + SM_KFIN);
    float*  dist = (float*) (smem + SM_DIST);

    const uint32_t sbA = smem_u32(sA);
    const uint32_t sbB = smem_u32(sB);

    const int tid  = threadIdx.x;
    const int warp = tid >> 5;
    const int lane = tid & 31;

    // ---- one-time: resident fp16 codebook + exact ||e||^2 ----
    for (int i = tid; i < K_DIM * D_DIM; i += THREADS) {
        int code = i >> 6, d = i & 63;
        sB[code * APITCH + d] = __float2half_rn(g_Et[i]);
    }
    {
        const float* er = g_Et + tid * D_DIM;              // THREADS == K_DIM
        float s = 0.f;
        #pragma unroll 8
        for (int d = 0; d < D_DIM; d++) s = fmaf(er[d], er[d], s);
        se2s[tid] = s;
    }
    __syncthreads();

    const int mi = warp & 3;       // M block: rows mi*16..+15
    const int wn = warp >> 2;      // N block: cols wn*128..+127
    const int rA = mi * 16 + (lane >> 2);   // this lane's first output row

    // precomputed ldsm addresses (byte offsets): per nb step +8*APITCH*2, per kb +32
    const uint32_t bAddr0 = sbB + ((wn * 128 + (lane & 7)) * APITCH) * 2
                          + ((lane >> 3) & 1) * 16;
    const uint32_t aAddr0 = sbA + ((mi * 16 + (lane & 15)) * APITCH) * 2
                          + (lane >> 4) * 16;

    for (int tile = blockIdx.x; tile < ntiles; tile += gridDim.x) {
        const int rowbase = tile * TILE_ROWS;

        // ---- load x tile as fp16(-2x) ----
        for (int i = tid; i < TILE_ROWS * D_DIM / 4; i += THREADS) {
            int row = i >> 4, d = (i & 15) * 4;
            int grow = rowbase + row;
            float4 v = (grow < nrows) ? __ldg((const float4*)(x + (size_t)grow * D_DIM + d))
                                      : make_float4(0.f, 0.f, 0.f, 0.f);
            __half2 h0 = __floats2half2_rn(-2.f * v.x, -2.f * v.y);
            __half2 h1 = __floats2half2_rn(-2.f * v.z, -2.f * v.w);
            uint2 pk = make_uint2(*(uint32_t*)&h0, *(uint32_t*)&h1);
            *(uint2*)(sA + row * APITCH + d) = pk;
        }
        __syncthreads();

        // ---- MMA mainloop: double-buffered B fragments (hide LDS latency) ----
        uint32_t afr[4][4];
        #pragma unroll
        for (int kb = 0; kb < 4; kb++)
            ldsm_x4(afr[kb], aAddr0 + kb * 32);

        float mvA = 3.4e38f, mvB = 3.4e38f;

        uint32_t b0[4][2], b1[4][2];
        #pragma unroll
        for (int kb = 0; kb < 4; kb++)               // preload nb = 0
            ldsm_x2(b0[kb], bAddr0 + kb * 32);

        #pragma unroll
        for (int nbp = 0; nbp < 8; nbp++) {          // pairs (nb, nb+1)
            const int nbe = 2 * nbp;
            // issue loads for nb+1 BEFORE consuming b0 (latency hidden behind MMA+epi)
            #pragma unroll
            for (int kb = 0; kb < 4; kb++)
                ldsm_x2(b1[kb], bAddr0 + (nbe + 1) * (8 * APITCH * 2) + kb * 32);

            {   // compute nb = nbe with b0
                float cacc[4] = {0.f, 0.f, 0.f, 0.f};
                #pragma unroll
                for (int kb = 0; kb < 4; kb++) mma16816(cacc, afr[kb], b0[kb]);
                int col0 = wn * 128 + nbe * 8 + (lane & 3) * 2;
                float2 e2 = *(const float2*)(se2s + col0);
                float s0 = cacc[0] + e2.x, s1 = cacc[1] + e2.y;
                float s2 = cacc[2] + e2.x, s3 = cacc[3] + e2.y;
                *(float2*)(dist + rA * DPITCH + col0)       = make_float2(s0, s1);
                *(float2*)(dist + (rA + 8) * DPITCH + col0) = make_float2(s2, s3);
                mvA = fminf(mvA, fminf(s0, s1));
                mvB = fminf(mvB, fminf(s2, s3));
            }

            // issue loads for nb+2 BEFORE consuming b1
            if (nbp < 7) {
                #pragma unroll
                for (int kb = 0; kb < 4; kb++)
                    ldsm_x2(b0[kb], bAddr0 + (nbe + 2) * (8 * APITCH * 2) + kb * 32);
            }

            {   // compute nb = nbe + 1 with b1
                float cacc[4] = {0.f, 0.f, 0.f, 0.f};
                #pragma unroll
                for (int kb = 0; kb < 4; kb++) mma16816(cacc, afr[kb], b1[kb]);
                int col0 = wn * 128 + (nbe + 1) * 8 + (lane & 3) * 2;
                float2 e2 = *(const float2*)(se2s + col0);
                float s0 = cacc[0] + e2.x, s1 = cacc[1] + e2.y;
                float s2 = cacc[2] + e2.x, s3 = cacc[3] + e2.y;
                *(float2*)(dist + rA * DPITCH + col0)       = make_float2(s0, s1);
                *(float2*)(dist + (rA + 8) * DPITCH + col0) = make_float2(s2, s3);
                mvA = fminf(mvA, fminf(s0, s1));
                mvB = fminf(mvB, fminf(s2, s3));
            }
        }

        // quad-reduce (lanes sharing a row differ only in lane&3)
        #pragma unroll
        for (int off = 1; off < 4; off <<= 1) {
            mvA = fminf(mvA, __shfl_xor_sync(0xffffffffu, mvA, off));
            mvB = fminf(mvB, __shfl_xor_sync(0xffffffffu, mvB, off));
        }
        if ((lane & 3) == 0) {
            pval[wn * 64 + rA]     = mvA;
            pval[wn * 64 + rA + 8] = mvB;
        }
        __syncthreads();

        // merge 4 N-block partials -> per-row threshold
        if (tid < TILE_ROWS) {
            float m = fminf(fminf(pval[tid], pval[64 + tid]),
                            fminf(pval[128 + tid], pval[192 + tid]));
            rthr[tid] = m + MARGIN;
        }
        __syncthreads();

        // ---- candidate scan + exact fp32 rescore (warp -> 4 rows) ----
        for (int rr = 0; rr < 4; rr++) {
            const int row = warp * 4 + rr;
            const int grow = rowbase + row;
            if (grow >= nrows) continue;                 // warp-uniform
            const float thr = rthr[row];
            const float* drow = dist + row * DPITCH;
            const float4* xr4 = (const float4*)(x + (size_t)grow * D_DIM);

            float ev = 3.4e38f; int ek = 0x7fffffff;
            #pragma unroll 1
            for (int j = 0; j < 16; j++) {
                int k = j * 32 + lane;
                if (drow[k] <= thr) {
                    const float4* er4 = (const float4*)(g_Et + k * D_DIM);
                    float d0 = 0.f, d1 = 0.f;
                    #pragma unroll 4
                    for (int q = 0; q < 16; q += 2) {
                        float4 ea = er4[q],     xa = __ldg(xr4 + q);
                        float4 eb = er4[q + 1], xb = __ldg(xr4 + q + 1);
                        d0 = fmaf(xa.x, ea.x, d0); d0 = fmaf(xa.y, ea.y, d0);
                        d0 = fmaf(xa.z, ea.z, d0); d0 = fmaf(xa.w, ea.w, d0);
                        d1 = fmaf(xb.x, eb.x, d1); d1 = fmaf(xb.y, eb.y, d1);
                        d1 = fmaf(xb.z, eb.z, d1); d1 = fmaf(xb.w, eb.w, d1);
                    }
                    float s = fmaf(-2.f, d0 + d1, se2s[k]);
                    if (s < ev || (s == ev && k < ek)) { ev = s; ek = k; }
                }
            }
            #pragma unroll
            for (int off = 16; off > 0; off >>= 1) {
                float ov = __shfl_down_sync(0xffffffffu, ev, off);
                int   ok = __shfl_down_sync(0xffffffffu, ek, off);
                if (ov < ev || (ov == ev && ok < ek)) { ev = ov; ek = ok; }
            }
            if (lane == 0) kfin[row] = ek;
        }
        __syncthreads();

        // ---- gather exact E row + store (4 threads/row x 16 floats) ----
        if (tid < TILE_ROWS * 4) {
            int row = tid >> 2, part = tid & 3;
            int grow = rowbase + row;
            if (grow < nrows) {
                const float4* src = (const float4*)(g_Et + kfin[row] * D_DIM + part * 16);
                float4* dst = (float4*)(out + (size_t)grow * D_DIM + part * 16);
                dst[0] = src[0]; dst[1] = src[1]; dst[2] = src[2]; dst[3] = src[3];
            }
        }
        __syncthreads();   // kfin/dist reuse guard for next tile
    }
}

extern "C" void kernel_launch(void* const* d_in, const int* in_sizes, int n_in,
                              void* d_out, int out_size)
{
    const float* x   = (const float*)d_in[0];   // inputs [B,H,W,D] fp32
    const float* emb = (const float*)d_in[1];   // embeddings [D,K] fp32
    float* out = (float*)d_out;

    int nrows  = in_sizes[0] / D_DIM;
    int ntiles = (nrows + TILE_ROWS - 1) / TILE_ROWS;

    vq_prep<<<(K_DIM * D_DIM + 511) / 512, 512>>>(emb);

    cudaFuncSetAttribute(vq_main, cudaFuncAttributeMaxDynamicSharedMemorySize, SM_TOTAL);
    int grid = NBLOCKS;
    if (grid > ntiles) grid = ntiles;
    vq_main<<<grid, THREADS, SM_TOTAL>>>(x, out, nrows, ntiles);
}